// round 15
// baseline (speedup 1.0000x reference)
#include <cuda_runtime.h>
#include <cstdint>

// KVDequantizer: Q4 nibble unpack + per-block(32) scale/bias.
// R7 (= R6 resubmitted after transient "device busy" infra failure):
// bulk-async (TMA 1D) 3-deep input pipeline, dequant in regs, direct
// coalesced STG.128 out. 8 CTAs/SM x 8 warps = 64 warps (100% occupancy).
//
// Inputs (metadata order):
//   d_in[0] k_packed int32 [2, 131072, 16]
//   d_in[1] k_scale  f32   [2, 131072, 1]
//   d_in[2] k_bias   f32   [2, 131072, 1]
//   d_in[3] v_packed int32 [2, 131072, 16]
//   d_in[4] v_scale  f32   [2, 131072, 1]
//   d_in[5] v_bias   f32   [2, 131072, 1]
// Output: [k_flat (8388608 f32) | v_flat (8388608 f32)]

#define TILE_ELEMS      4096                        // output floats per tile
#define IN_PACKED_B     (TILE_ELEMS * 2)            // 8192 B
#define SB_B            (TILE_ELEMS / 32 * 4)       // 512 B
#define IN_STAGE_B      (IN_PACKED_B + 2 * SB_B)    // 9216 B
#define NSTAGES         3
#define SMEM_MBAR       (NSTAGES * IN_STAGE_B)      // 27648
#define SMEM_TOTAL      (SMEM_MBAR + NSTAGES * 16)  // 27696

#define TILES_PER_TENSOR 2048
#define TOTAL_TILES      4096
#define CTAS_PER_SM      8
#define GRID             (152 * CTAS_PER_SM)        // 1216, persistent
#define NTHREADS         256
#define OUT_TILE_B       (TILE_ELEMS * 4)           // 16384 B

__device__ __forceinline__ uint32_t smem_u32(const void* p) {
    return (uint32_t)__cvta_generic_to_shared((void*)p);
}

__device__ __forceinline__ void mbar_init(uint32_t mbar, uint32_t count) {
    asm volatile("mbarrier.init.shared.b64 [%0], %1;" :: "r"(mbar), "r"(count) : "memory");
}

__device__ __forceinline__ void mbar_expect_tx(uint32_t mbar, uint32_t bytes) {
    asm volatile("mbarrier.arrive.expect_tx.shared.b64 _, [%0], %1;"
                 :: "r"(mbar), "r"(bytes) : "memory");
}

__device__ __forceinline__ void mbar_wait(uint32_t mbar, uint32_t parity) {
    uint32_t done;
    asm volatile(
        "{\n\t.reg .pred p;\n\t"
        "mbarrier.try_wait.parity.acquire.cta.shared::cta.b64 p, [%1], %2;\n\t"
        "selp.b32 %0, 1, 0, p;\n\t}"
        : "=r"(done) : "r"(mbar), "r"(parity) : "memory");
    if (!done) {
        asm volatile(
            "{\n\t.reg .pred P1;\n\t"
            "WL_%=:\n\t"
            "mbarrier.try_wait.parity.acquire.cta.shared::cta.b64 P1, [%0], %1, 0x989680;\n\t"
            "@P1 bra.uni WD_%=;\n\t"
            "bra.uni WL_%=;\n\t"
            "WD_%=:\n\t}"
            :: "r"(mbar), "r"(parity) : "memory");
    }
}

__device__ __forceinline__ void bulk_g2s(uint32_t smem_dst, const void* gmem_src,
                                         uint32_t bytes, uint32_t mbar) {
    asm volatile(
        "cp.async.bulk.shared::cta.global.mbarrier::complete_tx::bytes [%0], [%1], %2, [%3];"
        :: "r"(smem_dst), "l"(gmem_src), "r"(bytes), "r"(mbar) : "memory");
}

__global__ __launch_bounds__(NTHREADS, CTAS_PER_SM) void kv_dequant_tma3(
    const char* __restrict__ kp, const char* __restrict__ ks, const char* __restrict__ kb,
    const char* __restrict__ vp, const char* __restrict__ vs, const char* __restrict__ vb,
    char* __restrict__ out)
{
    extern __shared__ char smem[];
    const uint32_t sbase = smem_u32(smem);
    const int tid = threadIdx.x;

    if (tid == 0) {
        #pragma unroll
        for (int s = 0; s < NSTAGES; ++s)
            mbar_init(sbase + SMEM_MBAR + 16 * s, 1);
    }
    __syncthreads();

    auto issue_loads = [&](int t, int s) {
        int tensor = t >> 11;                       // 0 = k, 1 = v
        int local  = t & (TILES_PER_TENSOR - 1);
        const char* p  = tensor ? vp : kp;
        const char* sc = tensor ? vs : ks;
        const char* bi = tensor ? vb : kb;
        uint32_t mb  = sbase + SMEM_MBAR + 16 * s;
        uint32_t dst = sbase + s * IN_STAGE_B;
        mbar_expect_tx(mb, IN_STAGE_B);
        bulk_g2s(dst,                      p  + (size_t)local * IN_PACKED_B, IN_PACKED_B, mb);
        bulk_g2s(dst + IN_PACKED_B,        sc + (size_t)local * SB_B,        SB_B,        mb);
        bulk_g2s(dst + IN_PACKED_B + SB_B, bi + (size_t)local * SB_B,        SB_B,        mb);
    };

    // Prologue: prefetch up to NSTAGES-1 tiles.
    if (tid == 0) {
        #pragma unroll
        for (int d = 0; d < NSTAGES - 1; ++d) {
            int t = (int)blockIdx.x + d * GRID;
            if (t < TOTAL_TILES) issue_loads(t, d);
        }
    }

    int ph[NSTAGES] = {0, 0, 0};
    int it = 0;
    int sidx = 0;
    for (int t = blockIdx.x; t < TOTAL_TILES; t += GRID, ++it) {
        const int s = sidx;
        sidx = (sidx == NSTAGES - 1) ? 0 : sidx + 1;

        // Prefetch tile t + (NSTAGES-1)*GRID into the stage consumed at it-1
        // (freed by that iteration's trailing __syncthreads).
        const int tn = t + (NSTAGES - 1) * GRID;
        if (tid == 0 && tn < TOTAL_TILES) {
            int sp = s + NSTAGES - 1;
            if (sp >= NSTAGES) sp -= NSTAGES;
            issue_loads(tn, sp);
        }

        mbar_wait(sbase + SMEM_MBAR + 16 * s, ph[s]);
        ph[s] ^= 1;

        // Dequantize smem -> registers -> direct coalesced STG.
        const char*  in   = smem + s * IN_STAGE_B;
        const int2*  pin  = (const int2*)in;
        const float* psc  = (const float*)(in + IN_PACKED_B);
        const float* pbi  = (const float*)(in + IN_PACKED_B + SB_B);

        int tensor = t >> 11;
        int local  = t & (TILES_PER_TENSOR - 1);
        float4* po = (float4*)(out
                     + (size_t)tensor * ((size_t)TILES_PER_TENSOR * OUT_TILE_B)
                     + (size_t)local * OUT_TILE_B);

        #pragma unroll
        for (int r = 0; r < TILE_ELEMS / 4 / NTHREADS; ++r) {    // 4 iters
            int idx = r * NTHREADS + tid;                         // float4 idx 0..1023
            int2  x  = pin[idx];
            int   b  = idx >> 3;                                  // 8 float4 per block
            float sc = psc[b];
            float bi = pbi[b];
            float4 v;
            v.x = (float)( x.x       & 15) * sc + bi;
            v.y = (float)((x.x >> 4) & 15) * sc + bi;
            v.z = (float)( x.y       & 15) * sc + bi;
            v.w = (float)((x.y >> 4) & 15) * sc + bi;
            po[idx] = v;
        }

        // All threads done reading stage s before it can be refilled next wrap.
        __syncthreads();
    }
}

extern "C" void kernel_launch(void* const* d_in, const int* in_sizes, int n_in,
                              void* d_out, int out_size)
{
    const char* kp = (const char*)d_in[0];
    const char* ks = (const char*)d_in[1];
    const char* kb = (const char*)d_in[2];
    const char* vp = (const char*)d_in[3];
    const char* vs = (const char*)d_in[4];
    const char* vb = (const char*)d_in[5];

    cudaFuncSetAttribute(kv_dequant_tma3,
                         cudaFuncAttributeMaxDynamicSharedMemorySize, SMEM_TOTAL);

    kv_dequant_tma3<<<GRID, NTHREADS, SMEM_TOTAL>>>(
        kp, ks, kb, vp, vs, vb, (char*)d_out);
}

// round 16
// speedup vs baseline: 1.2937x; 1.2937x over previous
#include <cuda_runtime.h>
#include <cstdint>

// KVDequantizer: Q4 nibble unpack + per-block(32) scale/bias.
// R8: identical to bench-best R5 (TMA 4-deep input pipeline, dequant in regs,
// direct coalesced stores, 4 CTAs/SM) with ONE change: output stores use
// __stcs (evict-first). In the steady-state replay loop this keeps the 50 MB
// input set L2-resident instead of letting the 67 MB output stream thrash it.
//
// Inputs (metadata order):
//   d_in[0] k_packed int32 [2, 131072, 16]
//   d_in[1] k_scale  f32   [2, 131072, 1]
//   d_in[2] k_bias   f32   [2, 131072, 1]
//   d_in[3] v_packed int32 [2, 131072, 16]
//   d_in[4] v_scale  f32   [2, 131072, 1]
//   d_in[5] v_bias   f32   [2, 131072, 1]
// Output: [k_flat (8388608 f32) | v_flat (8388608 f32)]

#define TILE_ELEMS      4096                        // output floats per tile
#define IN_PACKED_B     (TILE_ELEMS * 2)            // 8192 B
#define SB_B            (TILE_ELEMS / 32 * 4)       // 512 B
#define IN_STAGE_B      (IN_PACKED_B + 2 * SB_B)    // 9216 B
#define NSTAGES         4
#define SMEM_MBAR       (NSTAGES * IN_STAGE_B)      // 36864
#define SMEM_TOTAL      (SMEM_MBAR + NSTAGES * 16)

#define TILES_PER_TENSOR 2048
#define TOTAL_TILES      4096
#define CTAS_PER_SM      4
#define GRID             (152 * CTAS_PER_SM)        // 608, persistent
#define NTHREADS        256
#define OUT_TILE_B      (TILE_ELEMS * 4)            // 16384 B

__device__ __forceinline__ uint32_t smem_u32(const void* p) {
    return (uint32_t)__cvta_generic_to_shared((void*)p);
}

__device__ __forceinline__ void mbar_init(uint32_t mbar, uint32_t count) {
    asm volatile("mbarrier.init.shared.b64 [%0], %1;" :: "r"(mbar), "r"(count) : "memory");
}

__device__ __forceinline__ void mbar_expect_tx(uint32_t mbar, uint32_t bytes) {
    asm volatile("mbarrier.arrive.expect_tx.shared.b64 _, [%0], %1;"
                 :: "r"(mbar), "r"(bytes) : "memory");
}

__device__ __forceinline__ void mbar_wait(uint32_t mbar, uint32_t parity) {
    uint32_t done;
    asm volatile(
        "{\n\t.reg .pred p;\n\t"
        "mbarrier.try_wait.parity.acquire.cta.shared::cta.b64 p, [%1], %2;\n\t"
        "selp.b32 %0, 1, 0, p;\n\t}"
        : "=r"(done) : "r"(mbar), "r"(parity) : "memory");
    if (!done) {
        asm volatile(
            "{\n\t.reg .pred P1;\n\t"
            "WL_%=:\n\t"
            "mbarrier.try_wait.parity.acquire.cta.shared::cta.b64 P1, [%0], %1, 0x989680;\n\t"
            "@P1 bra.uni WD_%=;\n\t"
            "bra.uni WL_%=;\n\t"
            "WD_%=:\n\t}"
            :: "r"(mbar), "r"(parity) : "memory");
    }
}

__device__ __forceinline__ void bulk_g2s(uint32_t smem_dst, const void* gmem_src,
                                         uint32_t bytes, uint32_t mbar) {
    asm volatile(
        "cp.async.bulk.shared::cta.global.mbarrier::complete_tx::bytes [%0], [%1], %2, [%3];"
        :: "r"(smem_dst), "l"(gmem_src), "r"(bytes), "r"(mbar) : "memory");
}

__global__ __launch_bounds__(NTHREADS, CTAS_PER_SM) void kv_dequant_tma4(
    const char* __restrict__ kp, const char* __restrict__ ks, const char* __restrict__ kb,
    const char* __restrict__ vp, const char* __restrict__ vs, const char* __restrict__ vb,
    char* __restrict__ out)
{
    extern __shared__ char smem[];
    const uint32_t sbase = smem_u32(smem);
    const int tid = threadIdx.x;

    if (tid == 0) {
        #pragma unroll
        for (int s = 0; s < NSTAGES; ++s)
            mbar_init(sbase + SMEM_MBAR + 16 * s, 1);
    }
    __syncthreads();

    auto issue_loads = [&](int t, int s) {
        int tensor = t >> 11;                       // 0 = k, 1 = v
        int local  = t & (TILES_PER_TENSOR - 1);
        const char* p  = tensor ? vp : kp;
        const char* sc = tensor ? vs : ks;
        const char* bi = tensor ? vb : kb;
        uint32_t mb  = sbase + SMEM_MBAR + 16 * s;
        uint32_t dst = sbase + s * IN_STAGE_B;
        mbar_expect_tx(mb, IN_STAGE_B);
        bulk_g2s(dst,                      p  + (size_t)local * IN_PACKED_B, IN_PACKED_B, mb);
        bulk_g2s(dst + IN_PACKED_B,        sc + (size_t)local * SB_B,        SB_B,        mb);
        bulk_g2s(dst + IN_PACKED_B + SB_B, bi + (size_t)local * SB_B,        SB_B,        mb);
    };

    // Prologue: prefetch up to NSTAGES-1 tiles.
    if (tid == 0) {
        #pragma unroll
        for (int d = 0; d < NSTAGES - 1; ++d) {
            int t = (int)blockIdx.x + d * GRID;
            if (t < TOTAL_TILES) issue_loads(t, d);
        }
    }

    int ph[NSTAGES] = {0, 0, 0, 0};
    int it = 0;
    for (int t = blockIdx.x; t < TOTAL_TILES; t += GRID, ++it) {
        const int s = it & (NSTAGES - 1);

        // Prefetch tile t + (NSTAGES-1)*GRID into the stage consumed at it-1
        // (freed by that iteration's trailing __syncthreads).
        const int tn = t + (NSTAGES - 1) * GRID;
        if (tid == 0 && tn < TOTAL_TILES)
            issue_loads(tn, (s + NSTAGES - 1) & (NSTAGES - 1));

        mbar_wait(sbase + SMEM_MBAR + 16 * s, ph[s]);
        ph[s] ^= 1;

        // Dequantize smem -> registers -> evict-first coalesced stores.
        const char*  in   = smem + s * IN_STAGE_B;
        const int2*  pin  = (const int2*)in;
        const float* psc  = (const float*)(in + IN_PACKED_B);
        const float* pbi  = (const float*)(in + IN_PACKED_B + SB_B);

        int tensor = t >> 11;
        int local  = t & (TILES_PER_TENSOR - 1);
        float4* po = (float4*)(out
                     + (size_t)tensor * ((size_t)TILES_PER_TENSOR * OUT_TILE_B)
                     + (size_t)local * OUT_TILE_B);

        #pragma unroll
        for (int r = 0; r < TILE_ELEMS / 4 / NTHREADS; ++r) {    // 4 iters
            int idx = r * NTHREADS + tid;                         // float4 idx 0..1023
            int2  x  = pin[idx];
            int   b  = idx >> 3;                                  // 8 float4 per block
            float sc = psc[b];
            float bi = pbi[b];
            float4 v;
            v.x = (float)( x.x       & 15) * sc + bi;
            v.y = (float)((x.x >> 4) & 15) * sc + bi;
            v.z = (float)( x.y       & 15) * sc + bi;
            v.w = (float)((x.y >> 4) & 15) * sc + bi;
            __stcs(po + idx, v);   // evict-first: don't let output thrash L2
        }

        // All threads done reading stage s before it can be refilled next wrap.
        __syncthreads();
    }
}

extern "C" void kernel_launch(void* const* d_in, const int* in_sizes, int n_in,
                              void* d_out, int out_size)
{
    const char* kp = (const char*)d_in[0];
    const char* ks = (const char*)d_in[1];
    const char* kb = (const char*)d_in[2];
    const char* vp = (const char*)d_in[3];
    const char* vs = (const char*)d_in[4];
    const char* vb = (const char*)d_in[5];

    cudaFuncSetAttribute(kv_dequant_tma4,
                         cudaFuncAttributeMaxDynamicSharedMemorySize, SMEM_TOTAL);

    kv_dequant_tma4<<<GRID, NTHREADS, SMEM_TOTAL>>>(
        kp, ks, kb, vp, vs, vb, (char*)d_out);
}